// round 2
// baseline (speedup 1.0000x reference)
#include <cuda_runtime.h>
#include <stdint.h>

#define BB   16
#define CH   3
#define HH   1024
#define WW   1024
#define NCRACK 8
#define NLINES (BB * NCRACK)            // 128
#define PIX    (HH * WW)                // 1048576
#define MASK_WORDS (BB * PIX / 32)      // 524288 words = 2MB

#define CRACK_VAL 0.05f

// 2MB crack bitmask: bit index = b*H*W + y*W + x
__device__ __align__(16) unsigned int g_maskbits[MASK_WORDS];

// ---------------------------------------------------------------------------
// Kernel 1: zero the bitmask (uint4 stores, 131072 threads)
// ---------------------------------------------------------------------------
__global__ void zero_mask_kernel() {
    unsigned i = blockIdx.x * blockDim.x + threadIdx.x;   // 0..131071
    reinterpret_cast<uint4*>(g_maskbits)[i] = make_uint4(0u, 0u, 0u, 0u);
}

// ---------------------------------------------------------------------------
// Kernel 2: rasterize all 128 crack lines, one thread per (line, t).
// Closed-form Bresenham matching the reference scan:
//   major axis advances every step; minor-axis step count at step t is
//   k(t) = max(0, ceil((2*t*d_min - d_maj) / (2*d_maj)))
// Proven to satisfy the reference recurrence exactly (incl. ties, dx==dy).
// ---------------------------------------------------------------------------
__global__ void raster_kernel(const int* __restrict__ ep) {
    int line = blockIdx.x;                                  // 0..127
    int t    = blockIdx.y * blockDim.x + threadIdx.x;       // 0..1023

    const int* e = ep + line * 4;                           // (y0,x0,y1,x1)
    int y0 = e[0], x0 = e[1], y1 = e[2], x1 = e[3];

    int dx = abs(x1 - x0);
    int dy = abs(y1 - y0);
    int sx = (x0 < x1) ? 1 : -1;
    int sy = (y0 < y1) ? 1 : -1;
    int ns = max(dx, dy);
    if (t > ns) return;

    int x, y;
    if (dx >= dy) {
        x = x0 + sx * t;
        int b2 = 2 * max(dx, 1);
        int a  = 2 * t * dy - dx;
        int k  = max(0, (a + b2 - 1) / b2);                 // ceil(a/b2), clamped
        y = y0 + sy * k;
    } else {
        y = y0 + sy * t;
        int b2 = 2 * dy;
        int a  = 2 * t * dx - dy;
        int k  = max(0, (a + b2 - 1) / b2);
        x = x0 + sx * k;
    }

    int b = line >> 3;                                      // line / NCRACK
    unsigned bit = (unsigned)(b * PIX + y * WW + x);
    atomicOr(&g_maskbits[bit >> 5], 1u << (bit & 31u));
}

// ---------------------------------------------------------------------------
// Kernel 3: fused apply — out = maskbit ? 0.05 : clamp(x, 0, 1)
// float4 vectorized; grid (W*H/4/256, C, B) so no index divisions.
// ---------------------------------------------------------------------------
__global__ void apply_kernel(const float4* __restrict__ x, float4* __restrict__ out) {
    unsigned p4 = blockIdx.x * blockDim.x + threadIdx.x;    // 0..262143 (pixel/4)
    unsigned c  = blockIdx.y;
    unsigned b  = blockIdx.z;

    unsigned idx     = (b * CH + c) * (PIX / 4) + p4;
    unsigned bitbase = b * PIX + p4 * 4u;
    unsigned word    = g_maskbits[bitbase >> 5];
    unsigned m       = word >> (bitbase & 31u);             // 4 bits, aligned (4 | 32)

    float4 v = x[idx];
    float4 r;
    r.x = (m & 1u) ? CRACK_VAL : fminf(fmaxf(v.x, 0.0f), 1.0f);
    r.y = (m & 2u) ? CRACK_VAL : fminf(fmaxf(v.y, 0.0f), 1.0f);
    r.z = (m & 4u) ? CRACK_VAL : fminf(fmaxf(v.z, 0.0f), 1.0f);
    r.w = (m & 8u) ? CRACK_VAL : fminf(fmaxf(v.w, 0.0f), 1.0f);
    out[idx] = r;
}

// ---------------------------------------------------------------------------
extern "C" void kernel_launch(void* const* d_in, const int* in_sizes, int n_in,
                              void* d_out, int out_size) {
    const float* x   = (const float*)d_in[0];   // [16,3,1024,1024] f32
    const int*   ep  = (const int*)d_in[1];     // [16,8,4] i32
    float*       out = (float*)d_out;

    // 1) zero 2MB bitmask
    zero_mask_kernel<<<MASK_WORDS / 4 / 256, 256>>>();

    // 2) rasterize 128 lines, one thread per (line, t)
    {
        dim3 grid(NLINES, (max(HH, WW) + 255) / 256);
        raster_kernel<<<grid, 256>>>(ep);
    }

    // 3) fused mask-apply + clip, float4 streaming
    {
        dim3 grid(PIX / 4 / 256, CH, BB);
        apply_kernel<<<grid, 256>>>((const float4*)x, (float4*)out);
    }
}